// round 13
// baseline (speedup 1.0000x reference)
#include <cuda_runtime.h>

#define TPB    256
#define NBINS  15
#define NCLS   16
#define NCELLS (NBINS * NCLS)   // 240
#define NBLK1  912              // 152 SMs * 6 blocks = one wave

// Per-cell accumulators (atomicAdd targets). Zero-initialized at module load;
// re-zeroed by ece_tail after each read -> graph-replay safe.
__device__ float g_cells[NCELLS];

__device__ __forceinline__ float tanh_approx(float x) {
    float r;
    asm("tanh.approx.f32 %0, %1;" : "=f"(r) : "f"(x));
    return r;
}

__device__ __forceinline__ void proc_pair(float2 xv, float2 tv,
                                          float (*acc)[NBINS][TPB], int tid) {
    // sigmoid(x) = 0.5*tanh(x/2) + 0.5  (single MUFU.TANH per element)
    float th0 = tanh_approx(xv.x * 0.5f);
    float th1 = tanh_approx(xv.y * 0.5f);
    float p0 = fmaf(0.5f, th0, 0.5f);
    float p1 = fmaf(0.5f, th1, 0.5f);
    // bin = floor(15*p) = floor(7.5*th + 7.5), clamped to 14
    int b0 = (int)fmaf(7.5f, th0, 7.5f); b0 = b0 > 14 ? 14 : b0;
    int b1 = (int)fmaf(7.5f, th1, 7.5f); b1 = b1 > 14 ? 14 : b1;
    acc[0][b0][tid] += p0 - tv.x;
    acc[1][b1][tid] += p1 - tv.y;
}

__global__ void __launch_bounds__(TPB, 6)
ece_accum(const float2* __restrict__ logits2, const float2* __restrict__ targets2, int n2) {
    // Private accumulators: acc[j][bin][tid], j = element parity within the
    // float2. class(element 2i+j) = 2*(i&7)+j, loop-invariant per (thread, j).
    // tid-major inner dim -> 4B lane stride -> conflict-free LDS/STS.
    __shared__ float acc[2][NBINS][TPB];
    const int tid = threadIdx.x;
    #pragma unroll
    for (int b = 0; b < NBINS; b++) { acc[0][b][tid] = 0.0f; acc[1][b][tid] = 0.0f; }
    __syncthreads();

    const int stride = NBLK1 * TPB;
    int i = blockIdx.x * TPB + tid;

    // 8-deep unroll: 16 batched LDG.64s in flight per warp before the
    // dependent tanh/bin/RMW tail.
    for (; i + 7 * stride < n2; i += 8 * stride) {
        float2 x0 = logits2[i];
        float2 x1 = logits2[i + stride];
        float2 x2 = logits2[i + 2 * stride];
        float2 x3 = logits2[i + 3 * stride];
        float2 x4 = logits2[i + 4 * stride];
        float2 x5 = logits2[i + 5 * stride];
        float2 x6 = logits2[i + 6 * stride];
        float2 x7 = logits2[i + 7 * stride];
        float2 t0 = targets2[i];
        float2 t1 = targets2[i + stride];
        float2 t2 = targets2[i + 2 * stride];
        float2 t3 = targets2[i + 3 * stride];
        float2 t4 = targets2[i + 4 * stride];
        float2 t5 = targets2[i + 5 * stride];
        float2 t6 = targets2[i + 6 * stride];
        float2 t7 = targets2[i + 7 * stride];
        proc_pair(x0, t0, acc, tid);
        proc_pair(x1, t1, acc, tid);
        proc_pair(x2, t2, acc, tid);
        proc_pair(x3, t3, acc, tid);
        proc_pair(x4, t4, acc, tid);
        proc_pair(x5, t5, acc, tid);
        proc_pair(x6, t6, acc, tid);
        proc_pair(x7, t7, acc, tid);
    }
    for (; i < n2; i += stride) {
        proc_pair(logits2[i], targets2[i], acc, tid);
    }
    __syncthreads();

    // Fold 2*256 private slots into 240 cells, then one spread-address
    // float atomic per cell (REDG; ~219K total chip-wide, negligible).
    // Cell = tid (< 240): bin b = tid>>4, class c = tid&15 = 2q+j
    // -> slots k*8+q, k=0..31.
    if (tid < NCELLS) {
        int b = tid >> 4;
        int c = tid & 15;
        int q = c >> 1;
        int j = c & 1;
        float s = 0.0f;
        #pragma unroll
        for (int k = 0; k < 32; k++) s += acc[j][b][k * 8 + q];
        atomicAdd(&g_cells[tid], s);
    }
}

// Kernel 2: one tiny block folds the 240 cell sums into the scalar and
// re-zeros g_cells for the next graph replay.
__global__ void __launch_bounds__(TPB, 1)
ece_tail(float* __restrict__ out, float inv_scale) {
    __shared__ float red[TPB];
    const int tid = threadIdx.x;
    float v = (tid < NCELLS) ? fabsf(g_cells[tid]) : 0.0f;
    red[tid] = v;
    __syncthreads();
    if (tid < NCELLS) g_cells[tid] = 0.0f;   // reset for next replay
    #pragma unroll
    for (int s = TPB / 2; s > 0; s >>= 1) {
        if (tid < s) red[tid] += red[tid + s];
        __syncthreads();
    }
    if (tid == 0) out[0] = red[0] * inv_scale;
}

extern "C" void kernel_launch(void* const* d_in, const int* in_sizes, int n_in,
                              void* d_out, int out_size) {
    const float2* logits2  = (const float2*)d_in[0];
    const float2* targets2 = (const float2*)d_in[1];
    float* out = (float*)d_out;
    const int n  = in_sizes[0];            // B*C = 33 554 432
    const int n2 = n >> 1;
    const float B = (float)(n / NCLS);

    ece_accum<<<NBLK1, TPB>>>(logits2, targets2, n2);
    // ECE = (sum over 240 cells of |sum(p - t)|) / B / NCELLS  (all nonempty)
    ece_tail<<<1, TPB>>>(out, 1.0f / (B * (float)NCELLS));
}

// round 16
// speedup vs baseline: 1.0145x; 1.0145x over previous
#include <cuda_runtime.h>

#define TPB    256
#define NBINS  15
#define NCLS   16
#define NCELLS (NBINS * NCLS)   // 240
#define NBLK1  912              // 152 SMs * 6 blocks = one wave

// Per-cell accumulators (atomicAdd targets). Zero-initialized at module load;
// re-zeroed by the last block after each read -> graph-replay safe.
__device__ float        g_cells[NCELLS];
__device__ unsigned int g_ticket = 0;

__device__ __forceinline__ float tanh_approx(float x) {
    float r;
    asm("tanh.approx.f32 %0, %1;" : "=f"(r) : "f"(x));
    return r;
}

__device__ __forceinline__ void proc_pair(float2 xv, float2 tv,
                                          float (*acc)[NBINS][TPB], int tid) {
    // sigmoid(x) = 0.5*tanh(x/2) + 0.5  (single MUFU.TANH per element)
    float th0 = tanh_approx(xv.x * 0.5f);
    float th1 = tanh_approx(xv.y * 0.5f);
    float p0 = fmaf(0.5f, th0, 0.5f);
    float p1 = fmaf(0.5f, th1, 0.5f);
    // bin = floor(15*p) = floor(7.5*th + 7.5), clamped to 14
    int b0 = (int)fmaf(7.5f, th0, 7.5f); b0 = b0 > 14 ? 14 : b0;
    int b1 = (int)fmaf(7.5f, th1, 7.5f); b1 = b1 > 14 ? 14 : b1;
    acc[0][b0][tid] += p0 - tv.x;
    acc[1][b1][tid] += p1 - tv.y;
}

__global__ void __launch_bounds__(TPB, 6)
ece_accum(const float2* __restrict__ logits2, const float2* __restrict__ targets2,
          int n2, float* __restrict__ out, float inv_scale) {
    // Private accumulators: acc[j][bin][tid], j = element parity within the
    // float2. class(element 2i+j) = 2*(i&7)+j, loop-invariant per (thread, j).
    // tid-major inner dim -> 4B lane stride -> conflict-free LDS/STS.
    __shared__ float acc[2][NBINS][TPB];
    const int tid = threadIdx.x;
    #pragma unroll
    for (int b = 0; b < NBINS; b++) { acc[0][b][tid] = 0.0f; acc[1][b][tid] = 0.0f; }
    __syncthreads();

    const int stride = NBLK1 * TPB;
    int i = blockIdx.x * TPB + tid;

    // 8-deep unroll: 16 batched LDG.64s in flight per warp before the
    // dependent tanh/bin/RMW tail.
    for (; i + 7 * stride < n2; i += 8 * stride) {
        float2 x0 = logits2[i];
        float2 x1 = logits2[i + stride];
        float2 x2 = logits2[i + 2 * stride];
        float2 x3 = logits2[i + 3 * stride];
        float2 x4 = logits2[i + 4 * stride];
        float2 x5 = logits2[i + 5 * stride];
        float2 x6 = logits2[i + 6 * stride];
        float2 x7 = logits2[i + 7 * stride];
        float2 t0 = targets2[i];
        float2 t1 = targets2[i + stride];
        float2 t2 = targets2[i + 2 * stride];
        float2 t3 = targets2[i + 3 * stride];
        float2 t4 = targets2[i + 4 * stride];
        float2 t5 = targets2[i + 5 * stride];
        float2 t6 = targets2[i + 6 * stride];
        float2 t7 = targets2[i + 7 * stride];
        proc_pair(x0, t0, acc, tid);
        proc_pair(x1, t1, acc, tid);
        proc_pair(x2, t2, acc, tid);
        proc_pair(x3, t3, acc, tid);
        proc_pair(x4, t4, acc, tid);
        proc_pair(x5, t5, acc, tid);
        proc_pair(x6, t6, acc, tid);
        proc_pair(x7, t7, acc, tid);
    }
    for (; i < n2; i += stride) {
        proc_pair(logits2[i], targets2[i], acc, tid);
    }
    __syncthreads();

    // Fold 2*256 private slots into 240 cells, then one spread-address
    // float atomic per cell (REDG; ~219K total chip-wide, negligible).
    // Cell = tid (< 240): bin b = tid>>4, class c = tid&15 = 2q+j
    // -> slots k*8+q, k=0..31.
    if (tid < NCELLS) {
        int b = tid >> 4;
        int c = tid & 15;
        int q = c >> 1;
        int j = c & 1;
        float s = 0.0f;
        #pragma unroll
        for (int k = 0; k < 32; k++) s += acc[j][b][k * 8 + q];
        atomicAdd(&g_cells[tid], s);
    }

    // Mini last-block finalize: last block folds the 240 cells to the scalar
    // and resets the globals for the next graph replay.
    __threadfence();
    __shared__ unsigned int rank_s;
    if (tid == 0) rank_s = atomicAdd(&g_ticket, 1u);
    __syncthreads();
    if (rank_s != (unsigned)(NBLK1 - 1)) return;

    float* red = &acc[0][0][0];   // reuse smem
    float v = (tid < NCELLS) ? fabsf(g_cells[tid]) : 0.0f;
    red[tid] = v;
    __syncthreads();
    if (tid < NCELLS) g_cells[tid] = 0.0f;   // reset for next replay
    #pragma unroll
    for (int s = TPB / 2; s > 0; s >>= 1) {
        if (tid < s) red[tid] += red[tid + s];
        __syncthreads();
    }
    if (tid == 0) {
        out[0] = red[0] * inv_scale;
        g_ticket = 0;   // reset for next replay
    }
}

extern "C" void kernel_launch(void* const* d_in, const int* in_sizes, int n_in,
                              void* d_out, int out_size) {
    const float2* logits2  = (const float2*)d_in[0];
    const float2* targets2 = (const float2*)d_in[1];
    float* out = (float*)d_out;
    const int n  = in_sizes[0];            // B*C = 33 554 432
    const int n2 = n >> 1;
    const float B = (float)(n / NCLS);

    // ECE = (sum over 240 cells of |sum(p - t)|) / B / NCELLS  (all nonempty)
    ece_accum<<<NBLK1, TPB>>>(logits2, targets2, n2, out, 1.0f / (B * (float)NCELLS));
}